// round 15
// baseline (speedup 1.0000x reference)
#include <cuda_runtime.h>
#include <cuda_fp16.h>
#include <math.h>
#include <stdint.h>

// ---------------- problem constants ----------------
#define B_   8
#define E_   8
#define C_   128
#define KW_  512
#define Mtot 16384          // B*L
#define KKd  4096           // KW*E
#define NNd  256            // 2*C

// ---------------- GEMM tiling ----------------
#define MT     64           // CTA M tile
#define KC     64           // K chunk (fp16 elems)
#define NCHUNK (KKd / KC)   // 64
#define NTH    288          // 8 consumer warps (2Mx4N, 32x64) + 1 producer warp
#define NCTA   (Mtot / MT)  // 256

// smem (bytes)
#define PITCH   144         // 64 fp16 data + 8 pad -> conflict-free ldmatrix
#define A_STG   (64 * PITCH)          // 9216 per stage
#define B_STG   (256 * PITCH)         // 36864 per stage
#define SM_A    0
#define SM_B    (2 * A_STG)           // 18432
#define SM_MBAR (SM_B + 2 * B_STG)    // 92160
#define SMEMSZ  (SM_MBAR + 32)        // 92192 -> 2 CTAs/SM
#define VPITCH  132                   // epilogue overlay [64][132] f32 = 33792B

// fp16 weights, [n][kk] K-major; n<128 -> W1, n>=128 -> W2
__device__ __half g_Bh[(size_t)NNd * KKd];

// ---------------- helpers ----------------
__device__ __forceinline__ uint32_t smem_u32(const void* p) {
    uint32_t a;
    asm("{ .reg .u64 t; cvta.to.shared.u64 t, %1; cvt.u32.u64 %0, t; }" : "=r"(a) : "l"(p));
    return a;
}
__device__ __forceinline__ uint32_t pack_h2(float x, float y) {
    __half2 t = __floats2half2_rn(x, y);
    return *reinterpret_cast<uint32_t*>(&t);
}
__device__ __forceinline__ void ldmx4(uint32_t* r, uint32_t addr) {
    asm volatile("ldmatrix.sync.aligned.m8n8.x4.shared.b16 {%0,%1,%2,%3}, [%4];"
                 : "=r"(r[0]), "=r"(r[1]), "=r"(r[2]), "=r"(r[3]) : "r"(addr));
}
__device__ __forceinline__ void mma16816(float* d, const uint32_t* a, uint32_t b0, uint32_t b1) {
    asm volatile("mma.sync.aligned.m16n8k16.row.col.f32.f16.f16.f32 "
                 "{%0,%1,%2,%3}, {%4,%5,%6,%7}, {%8,%9}, {%0,%1,%2,%3};"
                 : "+f"(d[0]), "+f"(d[1]), "+f"(d[2]), "+f"(d[3])
                 : "r"(a[0]), "r"(a[1]), "r"(a[2]), "r"(a[3]), "r"(b0), "r"(b1));
}
__device__ __forceinline__ void sts128(uint32_t a, uint32_t x, uint32_t y, uint32_t z, uint32_t w) {
    asm volatile("st.shared.v4.b32 [%0], {%1,%2,%3,%4};"
                 :: "r"(a), "r"(x), "r"(y), "r"(z), "r"(w) : "memory");
}
__device__ __forceinline__ void stsf2(uint32_t a, float x, float y) {
    asm volatile("st.shared.v2.f32 [%0], {%1,%2};" :: "r"(a), "f"(x), "f"(y) : "memory");
}
__device__ __forceinline__ void cpasync16(uint32_t dst, const void* src) {
    asm volatile("cp.async.cg.shared.global [%0], [%1], 16;" :: "r"(dst), "l"(src) : "memory");
}
__device__ __forceinline__ void cp_commit() { asm volatile("cp.async.commit_group;" ::: "memory"); }
__device__ __forceinline__ void cp_wait0() { asm volatile("cp.async.wait_group 0;" ::: "memory"); }
__device__ __forceinline__ void mbar_init(uint32_t a, uint32_t cnt) {
    asm volatile("mbarrier.init.shared.b64 [%0], %1;" :: "r"(a), "r"(cnt) : "memory");
}
__device__ __forceinline__ void mbar_arrive(uint32_t a) {
    asm volatile("mbarrier.arrive.shared.b64 _, [%0];" :: "r"(a) : "memory");
}
__device__ __forceinline__ void mbar_wait(uint32_t a, uint32_t parity) {
    uint32_t done;
    asm volatile("{ .reg .pred p; mbarrier.try_wait.parity.shared.b64 p, [%1], %2; selp.b32 %0, 1, 0, p; }"
                 : "=r"(done) : "r"(a), "r"(parity) : "memory");
    while (!done) {
        asm volatile("{ .reg .pred p; mbarrier.try_wait.parity.shared.b64 p, [%1], %2; selp.b32 %0, 1, 0, p; }"
                     : "=r"(done) : "r"(a), "r"(parity) : "memory");
    }
}
__device__ __forceinline__ void atomicMaxFloat(float* addr, float val) {
    if (val >= 0.0f) atomicMax((int*)addr, __float_as_int(val));
    else             atomicMin((unsigned int*)addr, __float_as_uint(val));
}

// ---------------- prep: weights -> fp16 [n][kk], coalesced; also init out ----------------
__global__ void prep_weights(const float* __restrict__ W1, const float* __restrict__ W2,
                             float* __restrict__ out) {
    int idx = blockIdx.x * blockDim.x + threadIdx.x;   // over C_*KW_ = 65536
    if (idx < B_ * C_) out[idx] = -INFINITY;
    if (idx >= C_ * KW_) return;
    int c = idx / KW_;
    int k = idx % KW_;
    uint32_t p1[4], p2[4];
#pragma unroll
    for (int e2 = 0; e2 < 4; e2++) {
        float a0 = W1[((size_t)c * E_ + 2 * e2) * KW_ + k];
        float a1 = W1[((size_t)c * E_ + 2 * e2 + 1) * KW_ + k];
        p1[e2] = pack_h2(a0, a1);
        float b0 = W2[((size_t)c * E_ + 2 * e2) * KW_ + k];
        float b1v = W2[((size_t)c * E_ + 2 * e2 + 1) * KW_ + k];
        p2[e2] = pack_h2(b0, b1v);
    }
    *(uint4*)&g_Bh[(size_t)c * KKd + k * E_]        = make_uint4(p1[0], p1[1], p1[2], p1[3]);
    *(uint4*)&g_Bh[(size_t)(C_ + c) * KKd + k * E_] = make_uint4(p2[0], p2[1], p2[2], p2[3]);
}

// ---------------- main fused GEMM + gate + max (warp-specialized) ----------------
__global__ __launch_bounds__(NTH, 2)
void gemm_gate_max(const float* __restrict__ Z,
                   const float* __restrict__ b1,
                   const float* __restrict__ b2,
                   float* __restrict__ out) {
    extern __shared__ char smem[];
    const uint32_t sb = smem_u32(smem);
    const int tid  = threadIdx.x;
    const int wid  = tid >> 5;
    const int lane = tid & 31;
    const int m_base = blockIdx.x * MT;

    const uint32_t mbFull0  = sb + SM_MBAR;
    const uint32_t mbFull1  = sb + SM_MBAR + 8;
    const uint32_t mbEmpty0 = sb + SM_MBAR + 16;
    const uint32_t mbEmpty1 = sb + SM_MBAR + 24;

    if (tid == 0) {
        mbar_init(mbFull0, 1);
        mbar_init(mbFull1, 1);
        mbar_init(mbEmpty0, 8);
        mbar_init(mbEmpty1, 8);
    }
    __syncthreads();

    float acc[2][8][4];
#pragma unroll
    for (int mi = 0; mi < 2; mi++)
#pragma unroll
        for (int ni = 0; ni < 8; ni++)
#pragma unroll
            for (int q = 0; q < 4; q++) acc[mi][ni][q] = 0.0f;

    const int wm = wid & 1;          // consumers only
    const int wn = wid >> 1;

    if (wid < 8) {
        // ================= consumers =================
        const uint32_t fragBase = (uint32_t)((lane % 16) * PITCH + (lane / 16) * 16);
        const uint32_t wmOff = (uint32_t)(wm * 32 * PITCH);
        const uint32_t wnOff = (uint32_t)(wn * 64 * PITCH);

        for (int j = 0; j < NCHUNK; ++j) {
            const int s = j & 1;
            const uint32_t par = (uint32_t)((j >> 1) & 1);
            mbar_wait(s ? mbFull1 : mbFull0, par);

            const uint32_t sA = sb + SM_A + (uint32_t)s * A_STG;
            const uint32_t sB = sb + SM_B + (uint32_t)s * B_STG;
#pragma unroll
            for (int ks = 0; ks < 4; ks++) {
                const uint32_t ko = (uint32_t)(ks * 32);
                uint32_t af[2][4], bf[4][4];
#pragma unroll
                for (int mi = 0; mi < 2; mi++)
                    ldmx4(af[mi], sA + wmOff + mi * (16 * PITCH) + ko + fragBase);
#pragma unroll
                for (int n2 = 0; n2 < 4; n2++)
                    ldmx4(bf[n2], sB + wnOff + n2 * (16 * PITCH) + ko + fragBase);
                if (ks == 3) {   // all reads of stage s issued -> release it
                    __syncwarp();
                    if (lane == 0) mbar_arrive(s ? mbEmpty1 : mbEmpty0);
                }
#pragma unroll
                for (int mi = 0; mi < 2; mi++)
#pragma unroll
                    for (int ni = 0; ni < 8; ni++)
                        mma16816(acc[mi][ni], af[mi], bf[ni >> 1][(ni & 1)], bf[ni >> 1][(ni & 1) + 2]);
            }
        }
    } else {
        // ================= producer (warp 8) =================
        const int nRow = lane >> 3;          // 0..3
        const int u    = lane & 7;
        const __half* bs0 = g_Bh + (size_t)nRow * KKd + u * 8;
        const uint32_t bd0 = (uint32_t)(nRow * PITCH + u * 16);
        const float*  as0 = Z + (size_t)(m_base + nRow) * KKd + u * 8;
        const uint32_t ad0 = bd0;

        // prologue: issue B(0) into stage 0
        {
            const uint32_t bb = sb + SM_B;
#pragma unroll 4
            for (int i = 0; i < 64; i++)
                cpasync16(bb + bd0 + (uint32_t)i * (4 * PITCH), bs0 + (size_t)i * (4 * KKd));
            cp_commit();
        }

        for (int j = 0; j < NCHUNK; ++j) {
            const int s = j & 1;
            const uint32_t aBase = sb + SM_A + (uint32_t)s * A_STG;

            // A(j): 16 granules/thread, batches of 4 (8 float4 in flight)
#pragma unroll 1
            for (int it = 0; it < 16; it += 4) {
                float4 v[8];
#pragma unroll
                for (int b = 0; b < 4; b++) {
                    const float* src = as0 + (size_t)(it + b) * (4 * KKd) + j * KC;
                    v[2 * b]     = *(const float4*)src;
                    v[2 * b + 1] = *(const float4*)(src + 4);
                }
#pragma unroll
                for (int b = 0; b < 4; b++)
                    sts128(aBase + ad0 + (uint32_t)(it + b) * (4 * PITCH),
                           pack_h2(v[2*b].x, v[2*b].y),   pack_h2(v[2*b].z, v[2*b].w),
                           pack_h2(v[2*b+1].x, v[2*b+1].y), pack_h2(v[2*b+1].z, v[2*b+1].w));
            }

            cp_wait0();          // B(j) complete (the only outstanding group)
            __syncwarp();
            if (lane == 0) mbar_arrive(s ? mbFull1 : mbFull0);

            if (j + 1 < NCHUNK) {
                if (j >= 1) {
                    // consumers must be done reading chunk j-1 (stage s^1)
                    mbar_wait((s ^ 1) ? mbEmpty1 : mbEmpty0, (uint32_t)(((j - 1) >> 1) & 1));
                }
                const uint32_t bb = sb + SM_B + (uint32_t)(s ^ 1) * B_STG;
                const __half* bsj = bs0 + (j + 1) * KC;
#pragma unroll 4
                for (int i = 0; i < 64; i++)
                    cpasync16(bb + bd0 + (uint32_t)i * (4 * PITCH), bsj + (size_t)i * (4 * KKd));
                cp_commit();
            }
        }
    }

    // ---- epilogue ----
    __syncthreads();   // pipe done; reuse smem as v2 tile [64][VPITCH] floats

    const int laneR = lane >> 2;
    const int laneC = (lane & 3) * 2;

    if (wid < 8 && wn >= 2) {
        // dump v2 half (global cols 128..255 -> tile cols 0..127)
#pragma unroll
        for (int mi = 0; mi < 2; mi++) {
#pragma unroll
            for (int ni = 0; ni < 8; ni++) {
                int r = wm * 32 + mi * 16 + laneR;
                int c = (wn - 2) * 64 + ni * 8 + laneC;
                uint32_t a0 = sb + (uint32_t)(r * (VPITCH * 4) + c * 4);
                stsf2(a0,                    acc[mi][ni][0], acc[mi][ni][1]);
                stsf2(a0 + 8 * (VPITCH * 4), acc[mi][ni][2], acc[mi][ni][3]);
            }
        }
    }
    __syncthreads();

    if (wid < 8 && wn < 2) {
        const float* sV = (const float*)smem;
        const int bidx = blockIdx.x >> 5;   // 32 CTAs per batch
        float gm[8][2];
#pragma unroll
        for (int ni = 0; ni < 8; ni++) {
            const int c = wn * 64 + ni * 8 + laneC;
            const float bb1a = __ldg(&b1[c]),     bb1b = __ldg(&b1[c + 1]);
            const float bb2a = __ldg(&b2[c]),     bb2b = __ldg(&b2[c + 1]);
            float m0 = -INFINITY, m1 = -INFINITY;
#pragma unroll
            for (int mi = 0; mi < 2; mi++) {
                int r0 = wm * 32 + mi * 16 + laneR;
                float v2a0 = sV[r0 * VPITCH + c]           + bb2a;
                float v2b0 = sV[r0 * VPITCH + c + 1]       + bb2b;
                float v2a1 = sV[(r0 + 8) * VPITCH + c]     + bb2a;
                float v2b1 = sV[(r0 + 8) * VPITCH + c + 1] + bb2b;
                float g0 = (acc[mi][ni][0] + bb1a) / (1.0f + __expf(-v2a0));
                float g1 = (acc[mi][ni][1] + bb1b) / (1.0f + __expf(-v2b0));
                float g2 = (acc[mi][ni][2] + bb1a) / (1.0f + __expf(-v2a1));
                float g3 = (acc[mi][ni][3] + bb1b) / (1.0f + __expf(-v2b1));
                m0 = fmaxf(m0, fmaxf(g0, g2));
                m1 = fmaxf(m1, fmaxf(g1, g3));
            }
            gm[ni][0] = m0;
            gm[ni][1] = m1;
        }
#pragma unroll
        for (int ni = 0; ni < 8; ni++) {
#pragma unroll
            for (int off = 4; off < 32; off <<= 1) {
                gm[ni][0] = fmaxf(gm[ni][0], __shfl_xor_sync(0xffffffffu, gm[ni][0], off));
                gm[ni][1] = fmaxf(gm[ni][1], __shfl_xor_sync(0xffffffffu, gm[ni][1], off));
            }
        }
        if (laneR == 0) {
#pragma unroll
            for (int ni = 0; ni < 8; ni++) {
                int c = wn * 64 + ni * 8 + laneC;
                atomicMaxFloat(&out[bidx * C_ + c],     gm[ni][0]);
                atomicMaxFloat(&out[bidx * C_ + c + 1], gm[ni][1]);
            }
        }
    }
}

extern "C" void kernel_launch(void* const* d_in, const int* in_sizes, int n_in,
                              void* d_out, int out_size) {
    const float* z  = (const float*)d_in[0];
    const float* W1 = (const float*)d_in[1];
    const float* b1 = (const float*)d_in[2];
    const float* W2 = (const float*)d_in[3];
    const float* b2 = (const float*)d_in[4];
    float* out = (float*)d_out;
    (void)in_sizes; (void)n_in; (void)out_size;

    cudaFuncSetAttribute(gemm_gate_max, cudaFuncAttributeMaxDynamicSharedMemorySize, SMEMSZ);

    prep_weights<<<(C_ * KW_ + 255) / 256, 256>>>(W1, W2, out);
    gemm_gate_max<<<NCTA, NTH, SMEMSZ>>>(z, b1, b2, out);
}

// round 16
// speedup vs baseline: 1.0007x; 1.0007x over previous
#include <cuda_runtime.h>
#include <cuda_fp16.h>
#include <math.h>
#include <stdint.h>

// ---------------- problem constants ----------------
#define B_   8
#define E_   8
#define C_   128
#define KW_  512
#define Mtot 16384          // B*L
#define KKd  4096           // KW*E
#define NNd  256            // 2*C

// ---------------- GEMM tiling ----------------
#define MT     64           // CTA M tile
#define KC     64           // K chunk (fp16 elems)
#define NCHUNK (KKd / KC)   // 64
#define NTH    288          // 8 consumer warps (2Mx4N, 32x64) + 1 producer warp
#define NCTA   (Mtot / MT)  // 256

// smem (bytes)
#define PITCH   144         // 64 fp16 data + 8 pad -> conflict-free ldmatrix
#define A_STG   (64 * PITCH)          // 9216 per stage
#define B_STG   (256 * PITCH)         // 36864 per stage
#define SM_A    0
#define SM_B    (2 * A_STG)           // 18432
#define SM_MBAR (SM_B + 2 * B_STG)    // 92160
#define SMEMSZ  (SM_MBAR + 32)        // 92192 -> 2 CTAs/SM
#define VPITCH  132                   // epilogue overlay [64][132] f32 = 33792B

// fp16 weights, [n][kk] K-major; n<128 -> W1, n>=128 -> W2
__device__ __half g_Bh[(size_t)NNd * KKd];

// ---------------- helpers ----------------
__device__ __forceinline__ uint32_t smem_u32(const void* p) {
    uint32_t a;
    asm("{ .reg .u64 t; cvta.to.shared.u64 t, %1; cvt.u32.u64 %0, t; }" : "=r"(a) : "l"(p));
    return a;
}
__device__ __forceinline__ uint32_t pack_h2(float x, float y) {
    __half2 t = __floats2half2_rn(x, y);
    return *reinterpret_cast<uint32_t*>(&t);
}
__device__ __forceinline__ void ldmx4(uint32_t* r, uint32_t addr) {
    asm volatile("ldmatrix.sync.aligned.m8n8.x4.shared.b16 {%0,%1,%2,%3}, [%4];"
                 : "=r"(r[0]), "=r"(r[1]), "=r"(r[2]), "=r"(r[3]) : "r"(addr));
}
__device__ __forceinline__ void mma16816(float* d, const uint32_t* a, uint32_t b0, uint32_t b1) {
    asm volatile("mma.sync.aligned.m16n8k16.row.col.f32.f16.f16.f32 "
                 "{%0,%1,%2,%3}, {%4,%5,%6,%7}, {%8,%9}, {%0,%1,%2,%3};"
                 : "+f"(d[0]), "+f"(d[1]), "+f"(d[2]), "+f"(d[3])
                 : "r"(a[0]), "r"(a[1]), "r"(a[2]), "r"(a[3]), "r"(b0), "r"(b1));
}
__device__ __forceinline__ void sts128(uint32_t a, uint32_t x, uint32_t y, uint32_t z, uint32_t w) {
    asm volatile("st.shared.v4.b32 [%0], {%1,%2,%3,%4};"
                 :: "r"(a), "r"(x), "r"(y), "r"(z), "r"(w) : "memory");
}
__device__ __forceinline__ void stsf2(uint32_t a, float x, float y) {
    asm volatile("st.shared.v2.f32 [%0], {%1,%2};" :: "r"(a), "f"(x), "f"(y) : "memory");
}
__device__ __forceinline__ void cpasync16(uint32_t dst, const void* src) {
    asm volatile("cp.async.cg.shared.global [%0], [%1], 16;" :: "r"(dst), "l"(src) : "memory");
}
__device__ __forceinline__ void cp_commit() { asm volatile("cp.async.commit_group;" ::: "memory"); }
__device__ __forceinline__ void cp_wait0() { asm volatile("cp.async.wait_group 0;" ::: "memory"); }
__device__ __forceinline__ void mbar_init(uint32_t a, uint32_t cnt) {
    asm volatile("mbarrier.init.shared.b64 [%0], %1;" :: "r"(a), "r"(cnt) : "memory");
}
__device__ __forceinline__ void mbar_arrive(uint32_t a) {
    asm volatile("mbarrier.arrive.shared.b64 _, [%0];" :: "r"(a) : "memory");
}
__device__ __forceinline__ void mbar_wait(uint32_t a, uint32_t parity) {
    uint32_t done;
    asm volatile("{ .reg .pred p; mbarrier.try_wait.parity.shared.b64 p, [%1], %2; selp.b32 %0, 1, 0, p; }"
                 : "=r"(done) : "r"(a), "r"(parity) : "memory");
    while (!done) {
        asm volatile("{ .reg .pred p; mbarrier.try_wait.parity.shared.b64 p, [%1], %2; selp.b32 %0, 1, 0, p; }"
                     : "=r"(done) : "r"(a), "r"(parity) : "memory");
    }
}
__device__ __forceinline__ void atomicMaxFloat(float* addr, float val) {
    if (val >= 0.0f) atomicMax((int*)addr, __float_as_int(val));
    else             atomicMin((unsigned int*)addr, __float_as_uint(val));
}

// ---------------- prep: weights -> fp16 [n][kk], coalesced; also init out ----------------
__global__ void prep_weights(const float* __restrict__ W1, const float* __restrict__ W2,
                             float* __restrict__ out) {
    int idx = blockIdx.x * blockDim.x + threadIdx.x;   // over C_*KW_ = 65536
    if (idx < B_ * C_) out[idx] = -INFINITY;
    if (idx >= C_ * KW_) return;
    int c = idx / KW_;
    int k = idx % KW_;
    uint32_t p1[4], p2[4];
#pragma unroll
    for (int e2 = 0; e2 < 4; e2++) {
        float a0 = W1[((size_t)c * E_ + 2 * e2) * KW_ + k];
        float a1 = W1[((size_t)c * E_ + 2 * e2 + 1) * KW_ + k];
        p1[e2] = pack_h2(a0, a1);
        float b0 = W2[((size_t)c * E_ + 2 * e2) * KW_ + k];
        float b1v = W2[((size_t)c * E_ + 2 * e2 + 1) * KW_ + k];
        p2[e2] = pack_h2(b0, b1v);
    }
    *(uint4*)&g_Bh[(size_t)c * KKd + k * E_]        = make_uint4(p1[0], p1[1], p1[2], p1[3]);
    *(uint4*)&g_Bh[(size_t)(C_ + c) * KKd + k * E_] = make_uint4(p2[0], p2[1], p2[2], p2[3]);
}

// ---------------- main fused GEMM + gate + max (warp-specialized) ----------------
__global__ __launch_bounds__(NTH, 2)
void gemm_gate_max(const float* __restrict__ Z,
                   const float* __restrict__ b1,
                   const float* __restrict__ b2,
                   float* __restrict__ out) {
    extern __shared__ char smem[];
    const uint32_t sb = smem_u32(smem);
    const int tid  = threadIdx.x;
    const int wid  = tid >> 5;
    const int lane = tid & 31;
    const int m_base = blockIdx.x * MT;

    const uint32_t mbFull0  = sb + SM_MBAR;
    const uint32_t mbFull1  = sb + SM_MBAR + 8;
    const uint32_t mbEmpty0 = sb + SM_MBAR + 16;
    const uint32_t mbEmpty1 = sb + SM_MBAR + 24;

    if (tid == 0) {
        mbar_init(mbFull0, 1);
        mbar_init(mbFull1, 1);
        mbar_init(mbEmpty0, 8);
        mbar_init(mbEmpty1, 8);
    }
    __syncthreads();

    float acc[2][8][4];
#pragma unroll
    for (int mi = 0; mi < 2; mi++)
#pragma unroll
        for (int ni = 0; ni < 8; ni++)
#pragma unroll
            for (int q = 0; q < 4; q++) acc[mi][ni][q] = 0.0f;

    const int wm = wid & 1;          // consumers only
    const int wn = wid >> 1;

    if (wid < 8) {
        // ================= consumers =================
        const uint32_t fragBase = (uint32_t)((lane % 16) * PITCH + (lane / 16) * 16);
        const uint32_t wmOff = (uint32_t)(wm * 32 * PITCH);
        const uint32_t wnOff = (uint32_t)(wn * 64 * PITCH);

        for (int j = 0; j < NCHUNK; ++j) {
            const int s = j & 1;
            const uint32_t par = (uint32_t)((j >> 1) & 1);
            mbar_wait(s ? mbFull1 : mbFull0, par);

            const uint32_t sA = sb + SM_A + (uint32_t)s * A_STG;
            const uint32_t sB = sb + SM_B + (uint32_t)s * B_STG;
#pragma unroll
            for (int ks = 0; ks < 4; ks++) {
                const uint32_t ko = (uint32_t)(ks * 32);
                uint32_t af[2][4], bf[4][4];
#pragma unroll
                for (int mi = 0; mi < 2; mi++)
                    ldmx4(af[mi], sA + wmOff + mi * (16 * PITCH) + ko + fragBase);
#pragma unroll
                for (int n2 = 0; n2 < 4; n2++)
                    ldmx4(bf[n2], sB + wnOff + n2 * (16 * PITCH) + ko + fragBase);
                if (ks == 3) {   // all reads of stage s issued -> release it
                    __syncwarp();
                    if (lane == 0) mbar_arrive(s ? mbEmpty1 : mbEmpty0);
                }
#pragma unroll
                for (int mi = 0; mi < 2; mi++)
#pragma unroll
                    for (int ni = 0; ni < 8; ni++)
                        mma16816(acc[mi][ni], af[mi], bf[ni >> 1][(ni & 1)], bf[ni >> 1][(ni & 1) + 2]);
            }
        }
    } else {
        // ================= producer (warp 8) =================
        const int nRow = lane >> 3;          // 0..3
        const int u    = lane & 7;
        const __half* bs0 = g_Bh + (size_t)nRow * KKd + u * 8;
        const uint32_t bd0 = (uint32_t)(nRow * PITCH + u * 16);
        const float*  as0 = Z + (size_t)(m_base + nRow) * KKd + u * 8;
        const uint32_t ad0 = bd0;

        // prologue: issue B(0) into stage 0
        {
            const uint32_t bb = sb + SM_B;
#pragma unroll 4
            for (int i = 0; i < 64; i++)
                cpasync16(bb + bd0 + (uint32_t)i * (4 * PITCH), bs0 + (size_t)i * (4 * KKd));
            cp_commit();
        }

        for (int j = 0; j < NCHUNK; ++j) {
            const int s = j & 1;
            const uint32_t aBase = sb + SM_A + (uint32_t)s * A_STG;

            // A(j): 16 granules/thread, batches of 4 (8 float4 in flight)
#pragma unroll 1
            for (int it = 0; it < 16; it += 4) {
                float4 v[8];
#pragma unroll
                for (int b = 0; b < 4; b++) {
                    const float* src = as0 + (size_t)(it + b) * (4 * KKd) + j * KC;
                    v[2 * b]     = *(const float4*)src;
                    v[2 * b + 1] = *(const float4*)(src + 4);
                }
#pragma unroll
                for (int b = 0; b < 4; b++)
                    sts128(aBase + ad0 + (uint32_t)(it + b) * (4 * PITCH),
                           pack_h2(v[2*b].x, v[2*b].y),   pack_h2(v[2*b].z, v[2*b].w),
                           pack_h2(v[2*b+1].x, v[2*b+1].y), pack_h2(v[2*b+1].z, v[2*b+1].w));
            }

            cp_wait0();          // B(j) complete (the only outstanding group)
            __syncwarp();
            if (lane == 0) mbar_arrive(s ? mbFull1 : mbFull0);

            if (j + 1 < NCHUNK) {
                if (j >= 1) {
                    // consumers must be done reading chunk j-1 (stage s^1)
                    mbar_wait((s ^ 1) ? mbEmpty1 : mbEmpty0, (uint32_t)(((j - 1) >> 1) & 1));
                }
                const uint32_t bb = sb + SM_B + (uint32_t)(s ^ 1) * B_STG;
                const __half* bsj = bs0 + (j + 1) * KC;
#pragma unroll 4
                for (int i = 0; i < 64; i++)
                    cpasync16(bb + bd0 + (uint32_t)i * (4 * PITCH), bsj + (size_t)i * (4 * KKd));
                cp_commit();
            }
        }
    }

    // ---- epilogue ----
    __syncthreads();   // pipe done; reuse smem as v2 tile [64][VPITCH] floats

    const int laneR = lane >> 2;
    const int laneC = (lane & 3) * 2;

    if (wid < 8 && wn >= 2) {
        // dump v2 half (global cols 128..255 -> tile cols 0..127)
#pragma unroll
        for (int mi = 0; mi < 2; mi++) {
#pragma unroll
            for (int ni = 0; ni < 8; ni++) {
                int r = wm * 32 + mi * 16 + laneR;
                int c = (wn - 2) * 64 + ni * 8 + laneC;
                uint32_t a0 = sb + (uint32_t)(r * (VPITCH * 4) + c * 4);
                stsf2(a0,                    acc[mi][ni][0], acc[mi][ni][1]);
                stsf2(a0 + 8 * (VPITCH * 4), acc[mi][ni][2], acc[mi][ni][3]);
            }
        }
    }
    __syncthreads();

    if (wid < 8 && wn < 2) {
        const float* sV = (const float*)smem;
        const int bidx = blockIdx.x >> 5;   // 32 CTAs per batch
        float gm[8][2];
#pragma unroll
        for (int ni = 0; ni < 8; ni++) {
            const int c = wn * 64 + ni * 8 + laneC;
            const float bb1a = __ldg(&b1[c]),     bb1b = __ldg(&b1[c + 1]);
            const float bb2a = __ldg(&b2[c]),     bb2b = __ldg(&b2[c + 1]);
            float m0 = -INFINITY, m1 = -INFINITY;
#pragma unroll
            for (int mi = 0; mi < 2; mi++) {
                int r0 = wm * 32 + mi * 16 + laneR;
                float v2a0 = sV[r0 * VPITCH + c]           + bb2a;
                float v2b0 = sV[r0 * VPITCH + c + 1]       + bb2b;
                float v2a1 = sV[(r0 + 8) * VPITCH + c]     + bb2a;
                float v2b1 = sV[(r0 + 8) * VPITCH + c + 1] + bb2b;
                float g0 = (acc[mi][ni][0] + bb1a) / (1.0f + __expf(-v2a0));
                float g1 = (acc[mi][ni][1] + bb1b) / (1.0f + __expf(-v2b0));
                float g2 = (acc[mi][ni][2] + bb1a) / (1.0f + __expf(-v2a1));
                float g3 = (acc[mi][ni][3] + bb1b) / (1.0f + __expf(-v2b1));
                m0 = fmaxf(m0, fmaxf(g0, g2));
                m1 = fmaxf(m1, fmaxf(g1, g3));
            }
            gm[ni][0] = m0;
            gm[ni][1] = m1;
        }
#pragma unroll
        for (int ni = 0; ni < 8; ni++) {
#pragma unroll
            for (int off = 4; off < 32; off <<= 1) {
                gm[ni][0] = fmaxf(gm[ni][0], __shfl_xor_sync(0xffffffffu, gm[ni][0], off));
                gm[ni][1] = fmaxf(gm[ni][1], __shfl_xor_sync(0xffffffffu, gm[ni][1], off));
            }
        }
        if (laneR == 0) {
#pragma unroll
            for (int ni = 0; ni < 8; ni++) {
                int c = wn * 64 + ni * 8 + laneC;
                atomicMaxFloat(&out[bidx * C_ + c],     gm[ni][0]);
                atomicMaxFloat(&out[bidx * C_ + c + 1], gm[ni][1]);
            }
        }
    }
}

extern "C" void kernel_launch(void* const* d_in, const int* in_sizes, int n_in,
                              void* d_out, int out_size) {
    const float* z  = (const float*)d_in[0];
    const float* W1 = (const float*)d_in[1];
    const float* b1 = (const float*)d_in[2];
    const float* W2 = (const float*)d_in[3];
    const float* b2 = (const float*)d_in[4];
    float* out = (float*)d_out;
    (void)in_sizes; (void)n_in; (void)out_size;

    cudaFuncSetAttribute(gemm_gate_max, cudaFuncAttributeMaxDynamicSharedMemorySize, SMEMSZ);

    prep_weights<<<(C_ * KW_ + 255) / 256, 256>>>(W1, W2, out);
    gemm_gate_max<<<NCTA, NTH, SMEMSZ>>>(z, b1, b2, out);
}

// round 17
// speedup vs baseline: 1.0008x; 1.0001x over previous
#include <cuda_runtime.h>
#include <cuda_fp16.h>
#include <math.h>
#include <stdint.h>

// ---------------- problem constants ----------------
#define B_   8
#define E_   8
#define C_   128
#define KW_  512
#define Mtot 16384          // B*L
#define KKd  4096           // KW*E
#define NNd  256            // 2*C

// ---------------- GEMM tiling ----------------
#define MT     64           // CTA M tile
#define KC     64           // K chunk (fp16 elems)
#define NCHUNK (KKd / KC)   // 64
#define NTH    288          // 8 consumer warps (2Mx4N, 32x64) + 1 producer warp
#define NCTA   (Mtot / MT)  // 256

// smem (bytes)
#define PITCH   144         // 64 fp16 data + 8 pad -> conflict-free ldmatrix
#define A_STG   (64 * PITCH)          // 9216 per stage
#define B_STG   (256 * PITCH)         // 36864 per stage
#define SM_A    0
#define SM_B    (2 * A_STG)           // 18432
#define SM_MBAR (SM_B + 2 * B_STG)    // 92160
#define SMEMSZ  (SM_MBAR + 32)        // 92192 -> 2 CTAs/SM
#define VPITCH  132                   // epilogue overlay [64][132] f32 = 33792B

// fp16 weights, [n][kk] K-major; n<128 -> W1, n>=128 -> W2
__device__ __half g_Bh[(size_t)NNd * KKd];

// ---------------- helpers ----------------
__device__ __forceinline__ uint32_t smem_u32(const void* p) {
    uint32_t a;
    asm("{ .reg .u64 t; cvta.to.shared.u64 t, %1; cvt.u32.u64 %0, t; }" : "=r"(a) : "l"(p));
    return a;
}
__device__ __forceinline__ uint32_t pack_h2(float x, float y) {
    __half2 t = __floats2half2_rn(x, y);
    return *reinterpret_cast<uint32_t*>(&t);
}
__device__ __forceinline__ void ldmx4(uint32_t* r, uint32_t addr) {
    asm volatile("ldmatrix.sync.aligned.m8n8.x4.shared.b16 {%0,%1,%2,%3}, [%4];"
                 : "=r"(r[0]), "=r"(r[1]), "=r"(r[2]), "=r"(r[3]) : "r"(addr));
}
__device__ __forceinline__ void mma16816(float* d, const uint32_t* a, uint32_t b0, uint32_t b1) {
    asm volatile("mma.sync.aligned.m16n8k16.row.col.f32.f16.f16.f32 "
                 "{%0,%1,%2,%3}, {%4,%5,%6,%7}, {%8,%9}, {%0,%1,%2,%3};"
                 : "+f"(d[0]), "+f"(d[1]), "+f"(d[2]), "+f"(d[3])
                 : "r"(a[0]), "r"(a[1]), "r"(a[2]), "r"(a[3]), "r"(b0), "r"(b1));
}
__device__ __forceinline__ void sts128(uint32_t a, uint32_t x, uint32_t y, uint32_t z, uint32_t w) {
    asm volatile("st.shared.v4.b32 [%0], {%1,%2,%3,%4};"
                 :: "r"(a), "r"(x), "r"(y), "r"(z), "r"(w) : "memory");
}
__device__ __forceinline__ void stsf2(uint32_t a, float x, float y) {
    asm volatile("st.shared.v2.f32 [%0], {%1,%2};" :: "r"(a), "f"(x), "f"(y) : "memory");
}
__device__ __forceinline__ void cpasync16(uint32_t dst, const void* src) {
    asm volatile("cp.async.cg.shared.global [%0], [%1], 16;" :: "r"(dst), "l"(src) : "memory");
}
__device__ __forceinline__ void cp_commit() { asm volatile("cp.async.commit_group;" ::: "memory"); }
__device__ __forceinline__ void cp_wait0() { asm volatile("cp.async.wait_group 0;" ::: "memory"); }
__device__ __forceinline__ void mbar_init(uint32_t a, uint32_t cnt) {
    asm volatile("mbarrier.init.shared.b64 [%0], %1;" :: "r"(a), "r"(cnt) : "memory");
}
__device__ __forceinline__ void mbar_arrive(uint32_t a) {
    asm volatile("mbarrier.arrive.shared.b64 _, [%0];" :: "r"(a) : "memory");
}
__device__ __forceinline__ void mbar_wait(uint32_t a, uint32_t parity) {
    uint32_t done;
    asm volatile("{ .reg .pred p; mbarrier.try_wait.parity.shared.b64 p, [%1], %2; selp.b32 %0, 1, 0, p; }"
                 : "=r"(done) : "r"(a), "r"(parity) : "memory");
    while (!done) {
        asm volatile("{ .reg .pred p; mbarrier.try_wait.parity.shared.b64 p, [%1], %2; selp.b32 %0, 1, 0, p; }"
                     : "=r"(done) : "r"(a), "r"(parity) : "memory");
    }
}
__device__ __forceinline__ void atomicMaxFloat(float* addr, float val) {
    if (val >= 0.0f) atomicMax((int*)addr, __float_as_int(val));
    else             atomicMin((unsigned int*)addr, __float_as_uint(val));
}

// ---------------- prep: weights -> fp16 [n][kk], coalesced; also init out ----------------
__global__ void prep_weights(const float* __restrict__ W1, const float* __restrict__ W2,
                             float* __restrict__ out) {
    int idx = blockIdx.x * blockDim.x + threadIdx.x;   // over C_*KW_ = 65536
    if (idx < B_ * C_) out[idx] = -INFINITY;
    if (idx >= C_ * KW_) return;
    int c = idx / KW_;
    int k = idx % KW_;
    uint32_t p1[4], p2[4];
#pragma unroll
    for (int e2 = 0; e2 < 4; e2++) {
        float a0 = W1[((size_t)c * E_ + 2 * e2) * KW_ + k];
        float a1 = W1[((size_t)c * E_ + 2 * e2 + 1) * KW_ + k];
        p1[e2] = pack_h2(a0, a1);
        float b0 = W2[((size_t)c * E_ + 2 * e2) * KW_ + k];
        float b1v = W2[((size_t)c * E_ + 2 * e2 + 1) * KW_ + k];
        p2[e2] = pack_h2(b0, b1v);
    }
    *(uint4*)&g_Bh[(size_t)c * KKd + k * E_]        = make_uint4(p1[0], p1[1], p1[2], p1[3]);
    *(uint4*)&g_Bh[(size_t)(C_ + c) * KKd + k * E_] = make_uint4(p2[0], p2[1], p2[2], p2[3]);
}

// ---------------- main fused GEMM + gate + max (warp-specialized) ----------------
__global__ __launch_bounds__(NTH, 2)
void gemm_gate_max(const float* __restrict__ Z,
                   const float* __restrict__ b1,
                   const float* __restrict__ b2,
                   float* __restrict__ out) {
    extern __shared__ char smem[];
    const uint32_t sb = smem_u32(smem);
    const int tid  = threadIdx.x;
    const int wid  = tid >> 5;
    const int lane = tid & 31;
    const int m_base = blockIdx.x * MT;

    const uint32_t mbFull0  = sb + SM_MBAR;
    const uint32_t mbFull1  = sb + SM_MBAR + 8;
    const uint32_t mbEmpty0 = sb + SM_MBAR + 16;
    const uint32_t mbEmpty1 = sb + SM_MBAR + 24;

    if (tid == 0) {
        mbar_init(mbFull0, 1);
        mbar_init(mbFull1, 1);
        mbar_init(mbEmpty0, 8);
        mbar_init(mbEmpty1, 8);
    }
    __syncthreads();

    float acc[2][8][4];
#pragma unroll
    for (int mi = 0; mi < 2; mi++)
#pragma unroll
        for (int ni = 0; ni < 8; ni++)
#pragma unroll
            for (int q = 0; q < 4; q++) acc[mi][ni][q] = 0.0f;

    const int wm = wid & 1;          // consumers only
    const int wn = wid >> 1;

    if (wid < 8) {
        // ================= consumers =================
        const uint32_t fragBase = (uint32_t)((lane % 16) * PITCH + (lane / 16) * 16);
        const uint32_t wmOff = (uint32_t)(wm * 32 * PITCH);
        const uint32_t wnOff = (uint32_t)(wn * 64 * PITCH);

        for (int j = 0; j < NCHUNK; ++j) {
            const int s = j & 1;
            const uint32_t par = (uint32_t)((j >> 1) & 1);
            mbar_wait(s ? mbFull1 : mbFull0, par);

            const uint32_t sA = sb + SM_A + (uint32_t)s * A_STG;
            const uint32_t sB = sb + SM_B + (uint32_t)s * B_STG;
#pragma unroll
            for (int ks = 0; ks < 4; ks++) {
                const uint32_t ko = (uint32_t)(ks * 32);
                uint32_t af[2][4], bf[4][4];
#pragma unroll
                for (int mi = 0; mi < 2; mi++)
                    ldmx4(af[mi], sA + wmOff + mi * (16 * PITCH) + ko + fragBase);
#pragma unroll
                for (int n2 = 0; n2 < 4; n2++)
                    ldmx4(bf[n2], sB + wnOff + n2 * (16 * PITCH) + ko + fragBase);
                if (ks == 3) {   // all reads of stage s issued -> release it
                    __syncwarp();
                    if (lane == 0) mbar_arrive(s ? mbEmpty1 : mbEmpty0);
                }
#pragma unroll
                for (int mi = 0; mi < 2; mi++)
#pragma unroll
                    for (int ni = 0; ni < 8; ni++)
                        mma16816(acc[mi][ni], af[mi], bf[ni >> 1][(ni & 1)], bf[ni >> 1][(ni & 1) + 2]);
            }
        }
    } else {
        // ================= producer (warp 8) =================
        const int nRow = lane >> 3;          // 0..3
        const int u    = lane & 7;
        const __half* bs0 = g_Bh + (size_t)nRow * KKd + u * 8;
        const uint32_t bd0 = (uint32_t)(nRow * PITCH + u * 16);
        const float*  as0 = Z + (size_t)(m_base + nRow) * KKd + u * 8;
        const uint32_t ad0 = bd0;

        // prologue: issue B(0) into stage 0
        {
            const uint32_t bb = sb + SM_B;
#pragma unroll 4
            for (int i = 0; i < 64; i++)
                cpasync16(bb + bd0 + (uint32_t)i * (4 * PITCH), bs0 + (size_t)i * (4 * KKd));
            cp_commit();
        }

        for (int j = 0; j < NCHUNK; ++j) {
            const int s = j & 1;
            const uint32_t aBase = sb + SM_A + (uint32_t)s * A_STG;

            // A(j): 16 granules/thread, batches of 4 (8 float4 in flight)
#pragma unroll 1
            for (int it = 0; it < 16; it += 4) {
                float4 v[8];
#pragma unroll
                for (int b = 0; b < 4; b++) {
                    const float* src = as0 + (size_t)(it + b) * (4 * KKd) + j * KC;
                    v[2 * b]     = *(const float4*)src;
                    v[2 * b + 1] = *(const float4*)(src + 4);
                }
#pragma unroll
                for (int b = 0; b < 4; b++)
                    sts128(aBase + ad0 + (uint32_t)(it + b) * (4 * PITCH),
                           pack_h2(v[2*b].x, v[2*b].y),   pack_h2(v[2*b].z, v[2*b].w),
                           pack_h2(v[2*b+1].x, v[2*b+1].y), pack_h2(v[2*b+1].z, v[2*b+1].w));
            }

            cp_wait0();          // B(j) complete (the only outstanding group)
            __syncwarp();
            if (lane == 0) mbar_arrive(s ? mbFull1 : mbFull0);

            if (j + 1 < NCHUNK) {
                if (j >= 1) {
                    // consumers must be done reading chunk j-1 (stage s^1)
                    mbar_wait((s ^ 1) ? mbEmpty1 : mbEmpty0, (uint32_t)(((j - 1) >> 1) & 1));
                }
                const uint32_t bb = sb + SM_B + (uint32_t)(s ^ 1) * B_STG;
                const __half* bsj = bs0 + (j + 1) * KC;
#pragma unroll 4
                for (int i = 0; i < 64; i++)
                    cpasync16(bb + bd0 + (uint32_t)i * (4 * PITCH), bsj + (size_t)i * (4 * KKd));
                cp_commit();
            }
        }
    }

    // ---- epilogue ----
    __syncthreads();   // pipe done; reuse smem as v2 tile [64][VPITCH] floats

    const int laneR = lane >> 2;
    const int laneC = (lane & 3) * 2;

    if (wid < 8 && wn >= 2) {
        // dump v2 half (global cols 128..255 -> tile cols 0..127)
#pragma unroll
        for (int mi = 0; mi < 2; mi++) {
#pragma unroll
            for (int ni = 0; ni < 8; ni++) {
                int r = wm * 32 + mi * 16 + laneR;
                int c = (wn - 2) * 64 + ni * 8 + laneC;
                uint32_t a0 = sb + (uint32_t)(r * (VPITCH * 4) + c * 4);
                stsf2(a0,                    acc[mi][ni][0], acc[mi][ni][1]);
                stsf2(a0 + 8 * (VPITCH * 4), acc[mi][ni][2], acc[mi][ni][3]);
            }
        }
    }
    __syncthreads();

    if (wid < 8 && wn < 2) {
        const float* sV = (const float*)smem;
        const int bidx = blockIdx.x >> 5;   // 32 CTAs per batch
        float gm[8][2];
#pragma unroll
        for (int ni = 0; ni < 8; ni++) {
            const int c = wn * 64 + ni * 8 + laneC;
            const float bb1a = __ldg(&b1[c]),     bb1b = __ldg(&b1[c + 1]);
            const float bb2a = __ldg(&b2[c]),     bb2b = __ldg(&b2[c + 1]);
            float m0 = -INFINITY, m1 = -INFINITY;
#pragma unroll
            for (int mi = 0; mi < 2; mi++) {
                int r0 = wm * 32 + mi * 16 + laneR;
                float v2a0 = sV[r0 * VPITCH + c]           + bb2a;
                float v2b0 = sV[r0 * VPITCH + c + 1]       + bb2b;
                float v2a1 = sV[(r0 + 8) * VPITCH + c]     + bb2a;
                float v2b1 = sV[(r0 + 8) * VPITCH + c + 1] + bb2b;
                float g0 = (acc[mi][ni][0] + bb1a) / (1.0f + __expf(-v2a0));
                float g1 = (acc[mi][ni][1] + bb1b) / (1.0f + __expf(-v2b0));
                float g2 = (acc[mi][ni][2] + bb1a) / (1.0f + __expf(-v2a1));
                float g3 = (acc[mi][ni][3] + bb1b) / (1.0f + __expf(-v2b1));
                m0 = fmaxf(m0, fmaxf(g0, g2));
                m1 = fmaxf(m1, fmaxf(g1, g3));
            }
            gm[ni][0] = m0;
            gm[ni][1] = m1;
        }
#pragma unroll
        for (int ni = 0; ni < 8; ni++) {
#pragma unroll
            for (int off = 4; off < 32; off <<= 1) {
                gm[ni][0] = fmaxf(gm[ni][0], __shfl_xor_sync(0xffffffffu, gm[ni][0], off));
                gm[ni][1] = fmaxf(gm[ni][1], __shfl_xor_sync(0xffffffffu, gm[ni][1], off));
            }
        }
        if (laneR == 0) {
#pragma unroll
            for (int ni = 0; ni < 8; ni++) {
                int c = wn * 64 + ni * 8 + laneC;
                atomicMaxFloat(&out[bidx * C_ + c],     gm[ni][0]);
                atomicMaxFloat(&out[bidx * C_ + c + 1], gm[ni][1]);
            }
        }
    }
}

extern "C" void kernel_launch(void* const* d_in, const int* in_sizes, int n_in,
                              void* d_out, int out_size) {
    const float* z  = (const float*)d_in[0];
    const float* W1 = (const float*)d_in[1];
    const float* b1 = (const float*)d_in[2];
    const float* W2 = (const float*)d_in[3];
    const float* b2 = (const float*)d_in[4];
    float* out = (float*)d_out;
    (void)in_sizes; (void)n_in; (void)out_size;

    cudaFuncSetAttribute(gemm_gate_max, cudaFuncAttributeMaxDynamicSharedMemorySize, SMEMSZ);

    prep_weights<<<(C_ * KW_ + 255) / 256, 256>>>(W1, W2, out);
    gemm_gate_max<<<NCTA, NTH, SMEMSZ>>>(z, b1, b2, out);
}